// round 1
// baseline (speedup 1.0000x reference)
#include <cuda_runtime.h>

// Problem constants (fixed by the dataset)
#define NN   4096
#define FDIM 256
#define BB   8
#define WPR  (NN / 32)          // 128 bitmask words per adjacency row

// -------- scratch (static __device__ arrays; no allocation allowed) --------
__device__ unsigned g_adj[NN * WPR];                    // 2 MB adjacency bitmask
__device__ int      g_deg[NN];                          // dedup'd out-degree
__device__ float    g_inv[NN];                          // 1 / (deg + 1e-6)
__device__ float    g_xt[(size_t)BB * NN * FDIM];       // 32 MB transformed features

// ---------------------------------------------------------------------------
// Kernel 1: zero bitmask + degree
// ---------------------------------------------------------------------------
__global__ void k_zero() {
    int i = blockIdx.x * blockDim.x + threadIdx.x;
    if (i < NN * WPR) g_adj[i] = 0u;
    if (i < NN)       g_deg[i] = 0;
}

// ---------------------------------------------------------------------------
// Kernel 2: build adjacency bitmask with dedup'd degree count
// edge_index layout: [0..E) = src row, [E..2E) = dst row
// ---------------------------------------------------------------------------
__global__ void k_edges(const int* __restrict__ ei, int E) {
    int e = blockIdx.x * blockDim.x + threadIdx.x;
    if (e >= E) return;
    int src = ei[e];
    int dst = ei[E + e];
    unsigned mask = 1u << (dst & 31);
    unsigned old = atomicOr(&g_adj[src * WPR + (dst >> 5)], mask);
    if (!(old & mask)) atomicAdd(&g_deg[src], 1);
}

// ---------------------------------------------------------------------------
// Kernel 3: inverse normalization factor (matches reference: deg + 1e-6)
// ---------------------------------------------------------------------------
__global__ void k_inv() {
    int i = blockIdx.x * blockDim.x + threadIdx.x;
    if (i < NN) g_inv[i] = 1.0f / ((float)g_deg[i] + 1e-6f);
}

// ---------------------------------------------------------------------------
// Kernel 4: xt = x @ W   (M = B*N = 32768, K = 256, Nout = 256)
// Classic fp32 SGEMM: 128x128 block tile, BK=8, 8x8 per-thread micro-tile.
// A tile stored transposed with pad 132 (conflict-free STS + aligned LDS.128).
// ---------------------------------------------------------------------------
#define BM 128
#define BN 128
#define BK 8
#define APAD 132

__global__ void __launch_bounds__(256, 2)
k_gemm(const float* __restrict__ x, const float* __restrict__ w) {
    __shared__ float As[BK][APAD];   // [k][m], padded
    __shared__ float Bs[BK][BN];     // [k][n]

    const int tid = threadIdx.x;
    const int m0 = blockIdx.y * BM;
    const int n0 = blockIdx.x * BN;

    // compute-phase mapping: 16x16 thread grid, 8x8 outputs each
    const int tm = (tid >> 4) << 3;   // row offset in tile
    const int tn = (tid & 15) << 3;   // col offset in tile

    // A load mapping: 128 rows x 8 k -> 1 float4 per thread
    const int ar = tid >> 1;            // 0..127
    const int ac = (tid & 1) << 2;      // 0 or 4
    // B load mapping: 8 k x 128 n -> 1 float4 per thread
    const int bk = tid >> 5;            // 0..7
    const int bn = (tid & 31) << 2;     // 0..124

    float acc[8][8];
    #pragma unroll
    for (int i = 0; i < 8; i++)
        #pragma unroll
        for (int j = 0; j < 8; j++) acc[i][j] = 0.f;

    for (int k0 = 0; k0 < FDIM; k0 += BK) {
        // load A tile (transposed into smem)
        float4 av = *(const float4*)&x[(size_t)(m0 + ar) * FDIM + k0 + ac];
        As[ac + 0][ar] = av.x;
        As[ac + 1][ar] = av.y;
        As[ac + 2][ar] = av.z;
        As[ac + 3][ar] = av.w;
        // load B tile (direct)
        *(float4*)&Bs[bk][bn] =
            *(const float4*)&w[(size_t)(k0 + bk) * FDIM + n0 + bn];
        __syncthreads();

        #pragma unroll
        for (int k = 0; k < BK; k++) {
            float a[8], b[8];
            #pragma unroll
            for (int i = 0; i < 8; i++) a[i] = As[k][tm + i];
            #pragma unroll
            for (int j = 0; j < 8; j++) b[j] = Bs[k][tn + j];
            #pragma unroll
            for (int i = 0; i < 8; i++)
                #pragma unroll
                for (int j = 0; j < 8; j++)
                    acc[i][j] += a[i] * b[j];
        }
        __syncthreads();
    }

    #pragma unroll
    for (int i = 0; i < 8; i++) {
        float* dst = &g_xt[(size_t)(m0 + tm + i) * FDIM + n0 + tn];
        *(float4*)(dst)     = make_float4(acc[i][0], acc[i][1], acc[i][2], acc[i][3]);
        *(float4*)(dst + 4) = make_float4(acc[i][4], acc[i][5], acc[i][6], acc[i][7]);
    }
}

// ---------------------------------------------------------------------------
// Kernel 5: sparse aggregation via bitmask rows.
// block = (src, b); 256 threads = feature dim; per neighbor a coalesced
// 1 KB row read (L2-resident). Uniform branching across the block.
// ---------------------------------------------------------------------------
__global__ void k_agg(const float* __restrict__ bias, float* __restrict__ out) {
    const int src = blockIdx.x;    // 0..4095
    const int b   = blockIdx.y;    // 0..7
    const int f   = threadIdx.x;   // 0..255

    const unsigned* __restrict__ row = &g_adj[src * WPR];
    const float* __restrict__ xtb = &g_xt[(size_t)b * NN * FDIM];

    float acc = 0.f;
    #pragma unroll 4
    for (int wword = 0; wword < WPR; wword++) {
        unsigned bits = row[wword];
        while (bits) {
            int d = __ffs(bits) - 1;
            bits &= bits - 1;
            acc += xtb[(size_t)(wword * 32 + d) * FDIM + f];
        }
    }
    out[((size_t)b * NN + src) * FDIM + f] = acc * g_inv[src] + bias[f];
}

// ---------------------------------------------------------------------------
extern "C" void kernel_launch(void* const* d_in, const int* in_sizes, int n_in,
                              void* d_out, int out_size) {
    const float* x    = (const float*)d_in[0];   // (8, 4096, 256) f32
    const int*   ei   = (const int*)  d_in[1];   // (2, 131072) i32
    const float* w    = (const float*)d_in[2];   // (256, 256) f32
    const float* bias = (const float*)d_in[3];   // (256,) f32
    float* out = (float*)d_out;

    const int E = in_sizes[1] / 2;

    k_zero<<<(NN * WPR + 255) / 256, 256>>>();
    k_edges<<<(E + 255) / 256, 256>>>(ei, E);
    k_inv<<<(NN + 255) / 256, 256>>>();
    k_gemm<<<dim3(FDIM / BN, (BB * NN) / BM), 256>>>(x, w);
    k_agg<<<dim3(NN, BB), 256>>>(bias, out);
}

// round 2
// speedup vs baseline: 2.4576x; 2.4576x over previous
#include <cuda_runtime.h>

// Problem constants (fixed by the dataset)
#define NN   4096
#define FDIM 256
#define BB   8
#define WPR  (NN / 32)          // 128 bitmask words per adjacency row
#define MAXD 128                // neighbor-list slab stride (P[deg>128] ~ 1e-40)

// -------- scratch (static __device__ arrays; no allocation allowed) --------
__device__ unsigned g_adj[NN * WPR];                    // 2 MB adjacency bitmask (dedup)
__device__ int      g_deg[NN];                          // dedup'd out-degree / cursor
__device__ float    g_inv[NN];                          // 1 / (deg + 1e-6)
__device__ int      g_nbr[NN * MAXD];                   // 2 MB compacted neighbor lists
__device__ float    g_xt[(size_t)BB * NN * FDIM];       // 32 MB transformed features

// ---------------------------------------------------------------------------
// Kernel 1: zero bitmask + degree
// ---------------------------------------------------------------------------
__global__ void k_zero() {
    int i = blockIdx.x * blockDim.x + threadIdx.x;
    if (i < NN * WPR) g_adj[i] = 0u;
    if (i < NN)       g_deg[i] = 0;
}

// ---------------------------------------------------------------------------
// Kernel 2: build dedup'd neighbor lists.
// Bitmask atomicOr detects duplicates; atomicAdd on degree doubles as the
// compaction cursor. edge_index layout: [0..E) = src, [E..2E) = dst.
// ---------------------------------------------------------------------------
__global__ void k_edges(const int* __restrict__ ei, int E) {
    int e = blockIdx.x * blockDim.x + threadIdx.x;
    if (e >= E) return;
    int src = ei[e];
    int dst = ei[E + e];
    unsigned mask = 1u << (dst & 31);
    unsigned old = atomicOr(&g_adj[src * WPR + (dst >> 5)], mask);
    if (!(old & mask)) {
        int pos = atomicAdd(&g_deg[src], 1);
        if (pos < MAXD) g_nbr[src * MAXD + pos] = dst;
    }
}

// ---------------------------------------------------------------------------
// Kernel 3: inverse normalization factor (matches reference: deg + 1e-6)
// ---------------------------------------------------------------------------
__global__ void k_inv() {
    int i = blockIdx.x * blockDim.x + threadIdx.x;
    if (i < NN) g_inv[i] = 1.0f / ((float)g_deg[i] + 1e-6f);
}

// ---------------------------------------------------------------------------
// Kernel 4: xt = x @ W   (M = B*N = 32768, K = 256, Nout = 256)
// fp32 SGEMM: 128x128 block tile, BK=8, 8x8 per-thread micro-tile.
// ---------------------------------------------------------------------------
#define BM 128
#define BN 128
#define BK 8
#define APAD 132

__global__ void __launch_bounds__(256, 2)
k_gemm(const float* __restrict__ x, const float* __restrict__ w) {
    __shared__ float As[BK][APAD];   // [k][m], padded
    __shared__ float Bs[BK][BN];     // [k][n]

    const int tid = threadIdx.x;
    const int m0 = blockIdx.y * BM;
    const int n0 = blockIdx.x * BN;

    const int tm = (tid >> 4) << 3;
    const int tn = (tid & 15) << 3;

    const int ar = tid >> 1;
    const int ac = (tid & 1) << 2;
    const int bk = tid >> 5;
    const int bn = (tid & 31) << 2;

    float acc[8][8];
    #pragma unroll
    for (int i = 0; i < 8; i++)
        #pragma unroll
        for (int j = 0; j < 8; j++) acc[i][j] = 0.f;

    for (int k0 = 0; k0 < FDIM; k0 += BK) {
        float4 av = *(const float4*)&x[(size_t)(m0 + ar) * FDIM + k0 + ac];
        As[ac + 0][ar] = av.x;
        As[ac + 1][ar] = av.y;
        As[ac + 2][ar] = av.z;
        As[ac + 3][ar] = av.w;
        *(float4*)&Bs[bk][bn] =
            *(const float4*)&w[(size_t)(k0 + bk) * FDIM + n0 + bn];
        __syncthreads();

        #pragma unroll
        for (int k = 0; k < BK; k++) {
            float a[8], b[8];
            #pragma unroll
            for (int i = 0; i < 8; i++) a[i] = As[k][tm + i];
            #pragma unroll
            for (int j = 0; j < 8; j++) b[j] = Bs[k][tn + j];
            #pragma unroll
            for (int i = 0; i < 8; i++)
                #pragma unroll
                for (int j = 0; j < 8; j++)
                    acc[i][j] += a[i] * b[j];
        }
        __syncthreads();
    }

    #pragma unroll
    for (int i = 0; i < 8; i++) {
        float* dst = &g_xt[(size_t)(m0 + tm + i) * FDIM + n0 + tn];
        *(float4*)(dst)     = make_float4(acc[i][0], acc[i][1], acc[i][2], acc[i][3]);
        *(float4*)(dst + 4) = make_float4(acc[i][4], acc[i][5], acc[i][6], acc[i][7]);
    }
}

// ---------------------------------------------------------------------------
// Kernel 5: sparse aggregation over compacted neighbor lists.
// block = src; 256 threads = feature dim; all 8 batches accumulated in
// registers per neighbor -> 8 independent coalesced 1KB row reads per
// iteration (MLP ~8-16 hides L2 latency). Neighbor list staged in smem.
// ---------------------------------------------------------------------------
__global__ void __launch_bounds__(256)
k_agg(const float* __restrict__ bias, float* __restrict__ out) {
    const int src = blockIdx.x;    // 0..4095
    const int f   = threadIdx.x;   // 0..255

    __shared__ int snb[MAXD];
    int deg = g_deg[src];
    if (deg > MAXD) deg = MAXD;
    if (f < deg) snb[f] = g_nbr[src * MAXD + f];
    __syncthreads();

    const float inv = g_inv[src];
    const float bf  = bias[f];

    float acc[BB];
    #pragma unroll
    for (int b = 0; b < BB; b++) acc[b] = 0.f;

    const size_t batch_stride = (size_t)NN * FDIM;

    int i = 0;
    // 2-way unrolled neighbor loop: 16 outstanding loads
    for (; i + 2 <= deg; i += 2) {
        const float* p0 = &g_xt[(size_t)snb[i]     * FDIM + f];
        const float* p1 = &g_xt[(size_t)snb[i + 1] * FDIM + f];
        float v0[BB], v1[BB];
        #pragma unroll
        for (int b = 0; b < BB; b++) v0[b] = p0[b * batch_stride];
        #pragma unroll
        for (int b = 0; b < BB; b++) v1[b] = p1[b * batch_stride];
        #pragma unroll
        for (int b = 0; b < BB; b++) acc[b] += v0[b] + v1[b];
    }
    if (i < deg) {
        const float* p0 = &g_xt[(size_t)snb[i] * FDIM + f];
        #pragma unroll
        for (int b = 0; b < BB; b++) acc[b] += p0[b * batch_stride];
    }

    #pragma unroll
    for (int b = 0; b < BB; b++)
        out[((size_t)b * NN + src) * FDIM + f] = acc[b] * inv + bf;
}

// ---------------------------------------------------------------------------
extern "C" void kernel_launch(void* const* d_in, const int* in_sizes, int n_in,
                              void* d_out, int out_size) {
    const float* x    = (const float*)d_in[0];   // (8, 4096, 256) f32
    const int*   ei   = (const int*)  d_in[1];   // (2, 131072) i32
    const float* w    = (const float*)d_in[2];   // (256, 256) f32
    const float* bias = (const float*)d_in[3];   // (256,) f32
    float* out = (float*)d_out;

    const int E = in_sizes[1] / 2;

    k_zero<<<(NN * WPR + 255) / 256, 256>>>();
    k_edges<<<(E + 255) / 256, 256>>>(ei, E);
    k_inv<<<(NN + 255) / 256, 256>>>();
    k_gemm<<<dim3(FDIM / BN, (BB * NN) / BM), 256>>>(x, w);
    k_agg<<<NN, 256>>>(bias, out);
}